// round 2
// baseline (speedup 1.0000x reference)
#include <cuda_runtime.h>
#include <cuda_bf16.h>

// Problem: softmask [B=16, K=64, H=240, W=320] fp32.
// out = sqrt( sum over 1024 slices of unbiased variance over H*W=76800 elems )
//
// Single fused kernel: one CTA per slice computes variance -> __device__
// scratch; last CTA to finish (atomic counter) reduces the 1024 variances,
// applies sqrt, writes the scalar. Counter is reset by the last CTA so the
// kernel is graph-replay safe and fully deterministic (fixed-order sums).

#define HW        76800          // 240*320
#define HW4       (HW / 4)       // 19200 float4 per slice
#define NSLICES   1024           // 16*64
#define NTHREADS  256

__device__ float        g_slice_var[NSLICES];
__device__ unsigned int g_count = 0;

__global__ __launch_bounds__(NTHREADS)
void loss_concentration_fused(const float4* __restrict__ in,
                              float* __restrict__ out) {
    const int s = blockIdx.x;
    const float4* __restrict__ p = in + (size_t)s * HW4;

    float sum = 0.f, sq = 0.f;

    // 19200 / 256 = 75 iterations per thread; unroll for MLP.
    #pragma unroll 5
    for (int i = threadIdx.x; i < HW4; i += NTHREADS) {
        float4 v = p[i];
        sum += (v.x + v.y) + (v.z + v.w);
        sq  += (v.x * v.x + v.y * v.y) + (v.z * v.z + v.w * v.w);
    }

    // warp reduce
    #pragma unroll
    for (int off = 16; off > 0; off >>= 1) {
        sum += __shfl_xor_sync(0xffffffffu, sum, off);
        sq  += __shfl_xor_sync(0xffffffffu, sq,  off);
    }

    __shared__ float s_sum[NTHREADS / 32];
    __shared__ float s_sq [NTHREADS / 32];
    __shared__ int   s_is_last;
    const int lane = threadIdx.x & 31;
    const int wid  = threadIdx.x >> 5;
    if (lane == 0) { s_sum[wid] = sum; s_sq[wid] = sq; }
    __syncthreads();

    if (threadIdx.x == 0) {
        float tsum = 0.f, tsq = 0.f;
        #pragma unroll
        for (int w = 0; w < NTHREADS / 32; w++) { tsum += s_sum[w]; tsq += s_sq[w]; }
        // unbiased: (sumsq - sum^2/n) / (n-1)
        float var = (tsq - tsum * tsum * (1.0f / (float)HW)) * (1.0f / (float)(HW - 1));
        g_slice_var[s] = var;
        __threadfence();                         // make var visible before count
        unsigned old = atomicAdd(&g_count, 1u);
        s_is_last = (old == NSLICES - 1) ? 1 : 0;
    }
    __syncthreads();

    if (s_is_last) {
        // Last CTA: reduce all 1024 variances. Read with .cg to bypass L1
        // (writers fenced to L2; this SM's L1 could otherwise be stale).
        float acc = 0.f;
        #pragma unroll
        for (int i = threadIdx.x; i < NSLICES; i += NTHREADS)
            acc += __ldcg(&g_slice_var[i]);

        #pragma unroll
        for (int off = 16; off > 0; off >>= 1)
            acc += __shfl_xor_sync(0xffffffffu, acc, off);

        __shared__ float s_acc[NTHREADS / 32];
        if (lane == 0) s_acc[wid] = acc;
        __syncthreads();

        if (threadIdx.x == 0) {
            float t = 0.f;
            #pragma unroll
            for (int w = 0; w < NTHREADS / 32; w++) t += s_acc[w];
            out[0] = sqrtf(t);
            g_count = 0;                         // reset for next graph replay
        }
    }
}

extern "C" void kernel_launch(void* const* d_in, const int* in_sizes, int n_in,
                              void* d_out, int out_size) {
    const float4* in = (const float4*)d_in[0];
    float* out = (float*)d_out;
    loss_concentration_fused<<<NSLICES, NTHREADS>>>(in, out);
}

// round 3
// speedup vs baseline: 1.0050x; 1.0050x over previous
#include <cuda_runtime.h>
#include <cuda_bf16.h>

// Problem: softmask [B=16, K=64, H=240, W=320] fp32.
// out = sqrt( sum over 1024 slices of unbiased variance over H*W=76800 elems )
//
// Each slice is split across PART=4 CTAs (4096 CTAs total, ~3.5 waves) to
// smooth the single-wave completion-time spread seen at DRAM=78.8%.
// Each CTA writes partial (sum, sumsq); the last CTA (atomic counter)
// combines partials per slice, computes variances, sums, sqrt -> scalar.
// Deterministic: fixed-order reductions, counter reset for graph replay.

#define HW        76800          // 240*320
#define HW4       (HW / 4)       // 19200 float4 per slice
#define NSLICES   1024           // 16*64
#define PART      4
#define CHUNK4    (HW4 / PART)   // 4800 float4 per CTA
#define NPARTS    (NSLICES * PART)
#define NTHREADS  256

__device__ float2       g_part[NPARTS];
__device__ unsigned int g_count = 0;

__global__ __launch_bounds__(NTHREADS)
void loss_concentration_fused(const float4* __restrict__ in,
                              float* __restrict__ out) {
    const int b     = blockIdx.x;
    const int slice = b >> 2;        // b / PART
    const int part  = b & (PART - 1);
    const float4* __restrict__ p =
        in + (size_t)slice * HW4 + (size_t)part * CHUNK4;

    float sum = 0.f, sq = 0.f;

    // 4800 / 256 = 18.75 iterations per thread; streaming (evict-first) loads.
    #pragma unroll 3
    for (int i = threadIdx.x; i < CHUNK4; i += NTHREADS) {
        float4 v = __ldcs(&p[i]);
        sum += (v.x + v.y) + (v.z + v.w);
        sq  += (v.x * v.x + v.y * v.y) + (v.z * v.z + v.w * v.w);
    }

    // warp reduce
    #pragma unroll
    for (int off = 16; off > 0; off >>= 1) {
        sum += __shfl_xor_sync(0xffffffffu, sum, off);
        sq  += __shfl_xor_sync(0xffffffffu, sq,  off);
    }

    __shared__ float s_sum[NTHREADS / 32];
    __shared__ float s_sq [NTHREADS / 32];
    __shared__ int   s_is_last;
    const int lane = threadIdx.x & 31;
    const int wid  = threadIdx.x >> 5;
    if (lane == 0) { s_sum[wid] = sum; s_sq[wid] = sq; }
    __syncthreads();

    if (threadIdx.x == 0) {
        float tsum = 0.f, tsq = 0.f;
        #pragma unroll
        for (int w = 0; w < NTHREADS / 32; w++) { tsum += s_sum[w]; tsq += s_sq[w]; }
        g_part[b] = make_float2(tsum, tsq);
        __threadfence();                         // partials visible before count
        unsigned old = atomicAdd(&g_count, 1u);
        s_is_last = (old == NPARTS - 1) ? 1 : 0;
    }
    __syncthreads();

    if (s_is_last) {
        // Last CTA: combine partials -> per-slice variance -> sum -> sqrt.
        // Thread t handles slices t, t+256, t+512, t+768 (fixed order).
        float acc = 0.f;
        #pragma unroll
        for (int r = 0; r < NSLICES / NTHREADS; r++) {
            const int s = threadIdx.x + r * NTHREADS;
            float tsum = 0.f, tsq = 0.f;
            #pragma unroll
            for (int q = 0; q < PART; q++) {
                float2 v = __ldcg(&g_part[s * PART + q]);  // bypass stale L1
                tsum += v.x;
                tsq  += v.y;
            }
            // unbiased: (sumsq - sum^2/n) / (n-1)
            acc += (tsq - tsum * tsum * (1.0f / (float)HW))
                   * (1.0f / (float)(HW - 1));
        }

        #pragma unroll
        for (int off = 16; off > 0; off >>= 1)
            acc += __shfl_xor_sync(0xffffffffu, acc, off);

        __shared__ float s_acc[NTHREADS / 32];
        if (lane == 0) s_acc[wid] = acc;
        __syncthreads();

        if (threadIdx.x == 0) {
            float t = 0.f;
            #pragma unroll
            for (int w = 0; w < NTHREADS / 32; w++) t += s_acc[w];
            out[0] = sqrtf(t);
            g_count = 0;                         // reset for next graph replay
        }
    }
}

extern "C" void kernel_launch(void* const* d_in, const int* in_sizes, int n_in,
                              void* d_out, int out_size) {
    const float4* in = (const float4*)d_in[0];
    float* out = (float*)d_out;
    loss_concentration_fused<<<NSLICES * PART, NTHREADS>>>(in, out);
}

// round 4
// speedup vs baseline: 1.0137x; 1.0087x over previous
#include <cuda_runtime.h>
#include <cuda_bf16.h>

// Problem: softmask [B=16, K=64, H=240, W=320] fp32.
// out = sqrt( sum over 1024 slices of unbiased variance over H*W=76800 elems )
//
// Streaming is at the B300 LTS ceiling (~6255 GB/s, grid-shape invariant),
// so this version minimizes the post-stream tail instead:
//   - one CTA per slice computes its variance locally
//   - cross-slice sum via FIXED-POINT atomicAdd (u64, var * 2^40):
//     integer adds are associative -> bit-deterministic in any arrival order,
//     and they overlap other CTAs' streaming.
//   - last CTA (counter) converts, sqrts, stores, resets (graph-replay safe).

#define HW        76800          // 240*320
#define HW4       (HW / 4)       // 19200 float4 per slice
#define NSLICES   1024           // 16*64
#define NTHREADS  256
#define FP_SCALE  1099511627776.0  // 2^40

__device__ unsigned long long g_acc   = 0ull;
__device__ unsigned int       g_count = 0;

__global__ __launch_bounds__(NTHREADS)
void loss_concentration_fused(const float4* __restrict__ in,
                              float* __restrict__ out) {
    const int s = blockIdx.x;
    const float4* __restrict__ p = in + (size_t)s * HW4;

    float sum = 0.f, sq = 0.f;

    // 19200 / 256 = 75 iterations per thread; streaming (evict-first) loads.
    #pragma unroll 5
    for (int i = threadIdx.x; i < HW4; i += NTHREADS) {
        float4 v = __ldcs(&p[i]);
        sum += (v.x + v.y) + (v.z + v.w);
        sq  += (v.x * v.x + v.y * v.y) + (v.z * v.z + v.w * v.w);
    }

    // warp reduce
    #pragma unroll
    for (int off = 16; off > 0; off >>= 1) {
        sum += __shfl_xor_sync(0xffffffffu, sum, off);
        sq  += __shfl_xor_sync(0xffffffffu, sq,  off);
    }

    __shared__ float s_sum[NTHREADS / 32];
    __shared__ float s_sq [NTHREADS / 32];
    const int lane = threadIdx.x & 31;
    const int wid  = threadIdx.x >> 5;
    if (lane == 0) { s_sum[wid] = sum; s_sq[wid] = sq; }
    __syncthreads();

    if (threadIdx.x == 0) {
        float tsum = 0.f, tsq = 0.f;
        #pragma unroll
        for (int w = 0; w < NTHREADS / 32; w++) { tsum += s_sum[w]; tsq += s_sq[w]; }
        // unbiased: (sumsq - sum^2/n) / (n-1)  -- non-negative by construction
        float var = (tsq - tsum * tsum * (1.0f / (float)HW))
                    * (1.0f / (float)(HW - 1));
        if (var < 0.f) var = 0.f;                // numerical guard
        // fixed-point contribution: deterministic under any atomic order
        unsigned long long q =
            (unsigned long long)(__double2ll_rn((double)var * FP_SCALE));
        atomicAdd(&g_acc, q);
        __threadfence();                         // acc visible before count
        unsigned old = atomicAdd(&g_count, 1u);
        if (old == NSLICES - 1) {
            // last CTA: finalize
            unsigned long long total = atomicAdd(&g_acc, 0ull);  // coherent read
            out[0] = sqrtf((float)((double)total * (1.0 / FP_SCALE)));
            g_acc   = 0ull;                      // reset for next graph replay
            g_count = 0;
        }
    }
}

extern "C" void kernel_launch(void* const* d_in, const int* in_sizes, int n_in,
                              void* d_out, int out_size) {
    const float4* in = (const float4*)d_in[0];
    float* out = (float*)d_out;
    loss_concentration_fused<<<NSLICES, NTHREADS>>>(in, out);
}